// round 8
// baseline (speedup 1.0000x reference)
#include <cuda_runtime.h>
#include <cuda_fp16.h>
#include <cuda_bf16.h>
#include <cstdint>
#include <cstddef>
#include <math.h>

#define T_STEPS 128
#define NB 256
#define NC 512
#define NH 512
#define NL 26
#define NCLS 6736
#define KDIM 512

#define NBLK 128
#define NTHR 256
#define NSLOTS (NL * 3)

#define PPAD 40
#define HPAD 520                        // padded h row (bf16 elems); 1040B stride
#define H_ELEMS (64 * HPAD)
#define RAW_BYTES (4 * 64 * PPAD * 2)   // 20480 B stage area (GEMM C needs 4 bufs)
#define DYN_SMEM (2 * H_ELEMS * 2 + RAW_BYTES)

typedef __nv_bfloat16 bf16;

// ---------------- scratch (device globals) ---------------------------------
__device__ __align__(256) bf16  g_feats_h[(size_t)T_STEPS * NB * NC];
__device__ __align__(256) bf16  g_feats_l[(size_t)T_STEPS * NB * NC];
__device__ __align__(256) __half g_fph[(size_t)T_STEPS * NB * NH];
__device__ __align__(256) __half g_featsh[(size_t)T_STEPS * NB * NC];
__device__ __align__(256) bf16  g_Wcat_h[4 * NH * NH];
__device__ __align__(256) bf16  g_Wcat_l[4 * NH * NH];
__device__ __align__(256) float g_bcat[4 * NH];
__device__ __align__(256) bf16  g_Wih_h[3 * NH * NC];
__device__ __align__(256) bf16  g_Wih_l[3 * NH * NC];
__device__ __align__(256) bf16  g_Wi2h_h[NH * NC];
__device__ __align__(256) bf16  g_Wi2h_l[NH * NC];
__device__ __align__(256) bf16  g_Wgen_h[(size_t)NCLS * NH];
__device__ __align__(256) bf16  g_Wgen_l[(size_t)NCLS * NH];
__device__ __align__(256) float g_hgh[2][NB * 4 * NH];   // double-buffered
__device__ __align__(256) float g_gi[NB * 3 * NH];
__device__ __align__(256) bf16  g_ctx_h[NB * NC];
__device__ __align__(256) bf16  g_ctx_l[NB * NC];
__device__ __align__(256) bf16  g_hs_h[(size_t)NB * NL * NH];
__device__ __align__(256) bf16  g_hs_l[(size_t)NB * NL * NH];
__device__ unsigned g_bar_cnt[NSLOTS];

// ---------------- fast activations -----------------------------------------
__device__ __forceinline__ float fast_tanh(float x) {
    float ax = fabsf(x);
    float e = __expf(-2.0f * ax);
    float r = __fdividef(1.0f - e, 1.0f + e);
    return copysignf(r, x);
}
__device__ __forceinline__ float fast_sigmoid(float x) {
    return __fdividef(1.0f, 1.0f + __expf(-x));
}
__device__ __forceinline__ void split_bf16(float x, bf16& hi, bf16& lo) {
    hi = __float2bfloat16(x);
    lo = __float2bfloat16(x - __bfloat162float(hi));
}

// ---------------- mma / ldmatrix primitives ---------------------------------
__device__ __forceinline__ void ldsm4(uint32_t* r, const bf16* p) {
    uint32_t addr = (uint32_t)__cvta_generic_to_shared(p);
    asm volatile("ldmatrix.sync.aligned.m8n8.x4.shared.b16 {%0,%1,%2,%3}, [%4];"
        : "=r"(r[0]), "=r"(r[1]), "=r"(r[2]), "=r"(r[3]) : "r"(addr));
}
__device__ __forceinline__ void mma_bf16(float* d, const uint32_t* a, const uint32_t* b) {
    asm volatile(
        "mma.sync.aligned.m16n8k16.row.col.f32.bf16.bf16.f32 "
        "{%0,%1,%2,%3}, {%4,%5,%6,%7}, {%8,%9}, {%0,%1,%2,%3};\n"
        : "+f"(d[0]), "+f"(d[1]), "+f"(d[2]), "+f"(d[3])
        : "r"(a[0]), "r"(a[1]), "r"(a[2]), "r"(a[3]), "r"(b[0]), "r"(b[1]));
}

// ---------------- device-wide barrier ---------------------------------------
__device__ __forceinline__ void gbar(int slot) {
    __syncthreads();
    if (threadIdx.x == 0) {
        __threadfence();
        atomicAdd(&g_bar_cnt[slot], 1u);
        unsigned v;
        do {
            asm volatile("ld.acquire.gpu.u32 %0, [%1];"
                         : "=r"(v) : "l"(&g_bar_cnt[slot]));
            if (v >= NBLK) break;
            __nanosleep(32);
        } while (true);
    }
    __syncthreads();
}

// ============ big GEMM (128x128) for i2h + generator ========================
template<bool OUT_HALF>
__global__ __launch_bounds__(256, 1) void gemm_bf16split(
    const bf16* __restrict__ Ah, const bf16* __restrict__ Al,
    const bf16* __restrict__ Bh, const bf16* __restrict__ Bl,
    const float* __restrict__ bias, void* __restrict__ Cv,
    int M, int N, int K)
{
    constexpr int PAD = 40;
    __shared__ bf16 sA[2][128 * PAD];
    __shared__ bf16 sB[2][128 * PAD];

    const int tid = threadIdx.x;
    const int bm = blockIdx.y * 128, bn = blockIdx.x * 128;
    const int warp = tid >> 5, lane = tid & 31;
    const int wm = (warp >> 2) * 64, wn = (warp & 3) * 32;

    float acc[4][4][4];
#pragma unroll
    for (int i = 0; i < 4; i++)
#pragma unroll
        for (int j = 0; j < 4; j++)
#pragma unroll
            for (int v = 0; v < 4; v++) acc[i][j][v] = 0.0f;

    const int row0 = tid >> 2, col0 = (tid & 3) * 8;
    const int row1 = (tid + 256) >> 2, col1 = ((tid + 256) & 3) * 8;

    uint4 pAh[2], pAl[2], pBh[2], pBl[2];

#define GLOAD(P, grow, gmax, koff) \
    (((grow) < (gmax)) ? *(const uint4*)((P) + (size_t)(grow) * K + (koff)) \
                       : make_uint4(0u, 0u, 0u, 0u))

    pAh[0] = GLOAD(Ah, bm + row0, M, col0); pAh[1] = GLOAD(Ah, bm + row1, M, col1);
    pAl[0] = GLOAD(Al, bm + row0, M, col0); pAl[1] = GLOAD(Al, bm + row1, M, col1);
    pBh[0] = GLOAD(Bh, bn + row0, N, col0); pBh[1] = GLOAD(Bh, bn + row1, N, col1);
    pBl[0] = GLOAD(Bl, bn + row0, N, col0); pBl[1] = GLOAD(Bl, bn + row1, N, col1);

    const int nk = K >> 5;
    for (int kt = 0; kt < nk; kt++) {
        const int off0 = row0 * PAD + col0, off1 = row1 * PAD + col1;
        *(uint4*)&sA[0][off0] = pAh[0]; *(uint4*)&sA[0][off1] = pAh[1];
        *(uint4*)&sA[1][off0] = pAl[0]; *(uint4*)&sA[1][off1] = pAl[1];
        *(uint4*)&sB[0][off0] = pBh[0]; *(uint4*)&sB[0][off1] = pBh[1];
        *(uint4*)&sB[1][off0] = pBl[0]; *(uint4*)&sB[1][off1] = pBl[1];
        __syncthreads();

        if (kt + 1 < nk) {
            const int k0 = (kt + 1) << 5;
            pAh[0] = GLOAD(Ah, bm + row0, M, k0 + col0); pAh[1] = GLOAD(Ah, bm + row1, M, k0 + col1);
            pAl[0] = GLOAD(Al, bm + row0, M, k0 + col0); pAl[1] = GLOAD(Al, bm + row1, M, k0 + col1);
            pBh[0] = GLOAD(Bh, bn + row0, N, k0 + col0); pBh[1] = GLOAD(Bh, bn + row1, N, k0 + col1);
            pBl[0] = GLOAD(Bl, bn + row0, N, k0 + col0); pBl[1] = GLOAD(Bl, bn + row1, N, k0 + col1);
        }

#pragma unroll
        for (int kc = 0; kc < 2; kc++) {
            uint32_t ah[4][4], al[4][4], bh[4][2], bl[4][2];
            const int acol = kc * 16 + (lane >> 4) * 8;
            const int arow = lane & 15;
#pragma unroll
            for (int mt = 0; mt < 4; mt++) {
                const int r = wm + mt * 16 + arow;
                ldsm4(ah[mt], &sA[0][r * PAD + acol]);
                ldsm4(al[mt], &sA[1][r * PAD + acol]);
            }
            const int bcol = kc * 16 + ((lane >> 3) & 1) * 8;
            const int brow = (lane & 7) + (lane >> 4) * 8;
#pragma unroll
            for (int q = 0; q < 2; q++) {
                const int r = wn + q * 16 + brow;
                uint32_t t[4];
                ldsm4(t, &sB[0][r * PAD + bcol]);
                bh[2 * q][0] = t[0]; bh[2 * q][1] = t[1];
                bh[2 * q + 1][0] = t[2]; bh[2 * q + 1][1] = t[3];
                ldsm4(t, &sB[1][r * PAD + bcol]);
                bl[2 * q][0] = t[0]; bl[2 * q][1] = t[1];
                bl[2 * q + 1][0] = t[2]; bl[2 * q + 1][1] = t[3];
            }
#pragma unroll
            for (int mt = 0; mt < 4; mt++)
#pragma unroll
                for (int nt = 0; nt < 4; nt++) {
                    mma_bf16(acc[mt][nt], ah[mt], bh[nt]);
                    mma_bf16(acc[mt][nt], ah[mt], bl[nt]);
                    mma_bf16(acc[mt][nt], al[mt], bh[nt]);
                }
        }
        __syncthreads();
    }
#undef GLOAD

    const int rbase = lane >> 2, cbase = (lane & 3) * 2;
#pragma unroll
    for (int mt = 0; mt < 4; mt++) {
#pragma unroll
        for (int nt = 0; nt < 4; nt++) {
            const int gm0 = bm + wm + mt * 16 + rbase;
            const int gm1 = gm0 + 8;
            const int gn = bn + wn + nt * 8 + cbase;
            if (gn >= N) continue;
            const float b0 = bias ? bias[gn] : 0.0f;
            const float b1 = bias ? bias[gn + 1] : 0.0f;
            const float v0 = acc[mt][nt][0] + b0, v1 = acc[mt][nt][1] + b1;
            const float v2 = acc[mt][nt][2] + b0, v3 = acc[mt][nt][3] + b1;
            if (OUT_HALF) {
                __half* C = (__half*)Cv;
                if (gm0 < M) *(__half2*)(C + (size_t)gm0 * N + gn) = __floats2half2_rn(v0, v1);
                if (gm1 < M) *(__half2*)(C + (size_t)gm1 * N + gn) = __floats2half2_rn(v2, v3);
            } else {
                float* C = (float*)Cv;
                if (gm0 < M) *(float2*)(C + (size_t)gm0 * N + gn) = make_float2(v0, v1);
                if (gm1 < M) *(float2*)(C + (size_t)gm1 * N + gn) = make_float2(v2, v3);
            }
        }
    }
}

// ============ persistent recurrence kernel ==================================
struct AttnSmem {
    float hp0[NH];
    float hp1[NH];
    float ws[NH];
    float e0[T_STEPS];
    float e1[T_STEPS];
    float rmax[8];
    float rsum[8];
};

// GEMM A: A-operand from persistent smem h (rows = CTA's own 64), B staged.
__device__ __forceinline__ void gemm_phaseA(
    const bf16* __restrict__ sh_hi, const bf16* __restrict__ sh_lo,
    const bf16* __restrict__ Bh, const bf16* __restrict__ Bl,
    const float* __restrict__ bias, float* __restrict__ C,
    int N, int bm, int bn, char* raw)
{
    bf16* sBh = (bf16*)raw;
    bf16* sBl = sBh + 64 * PPAD;

    const int tid = threadIdx.x;
    const int warp = tid >> 5, lane = tid & 31;
    const int wm = (warp & 1) * 32, wn = (warp >> 1) * 16;
    const int row = tid >> 2, col = (tid & 3) * 8;
    const size_t bbase = (size_t)(bn + row) * KDIM + col;
    const int soff = row * PPAD + col;

    float acc[2][2][4];
#pragma unroll
    for (int i = 0; i < 2; i++)
#pragma unroll
        for (int j = 0; j < 2; j++)
#pragma unroll
            for (int v = 0; v < 4; v++) acc[i][j][v] = 0.0f;

    uint4 pb0 = *(const uint4*)(Bh + bbase);
    uint4 pb1 = *(const uint4*)(Bl + bbase);

    const int nk = KDIM / 32;
    for (int kt = 0; kt < nk; kt++) {
        *(uint4*)&sBh[soff] = pb0; *(uint4*)&sBl[soff] = pb1;
        __syncthreads();

        if (kt + 1 < nk) {
            const int k0 = (kt + 1) * 32;
            pb0 = *(const uint4*)(Bh + bbase + k0);
            pb1 = *(const uint4*)(Bl + bbase + k0);
        }

#pragma unroll
        for (int kc = 0; kc < 2; kc++) {
            uint32_t ah[2][4], al[2][4], bh[2][2], bl[2][2];
            const int acol = kt * 32 + kc * 16 + (lane >> 4) * 8;  // abs k col
            const int arow = lane & 15;
#pragma unroll
            for (int mt = 0; mt < 2; mt++) {
                const int r = wm + mt * 16 + arow;
                ldsm4(ah[mt], &sh_hi[r * HPAD + acol]);
                ldsm4(al[mt], &sh_lo[r * HPAD + acol]);
            }
            const int bcol = kc * 16 + ((lane >> 3) & 1) * 8;
            const int brow = (lane & 7) + (lane >> 4) * 8;
            {
                const int r = wn + brow;
                uint32_t t[4];
                ldsm4(t, &sBh[r * PPAD + bcol]);
                bh[0][0] = t[0]; bh[0][1] = t[1];
                bh[1][0] = t[2]; bh[1][1] = t[3];
                ldsm4(t, &sBl[r * PPAD + bcol]);
                bl[0][0] = t[0]; bl[0][1] = t[1];
                bl[1][0] = t[2]; bl[1][1] = t[3];
            }
#pragma unroll
            for (int mt = 0; mt < 2; mt++)
#pragma unroll
                for (int np = 0; np < 2; np++) {
                    mma_bf16(acc[mt][np], ah[mt], bh[np]);
                    mma_bf16(acc[mt][np], ah[mt], bl[np]);
                    mma_bf16(acc[mt][np], al[mt], bh[np]);
                }
        }
        __syncthreads();
    }

    const int rb = lane >> 2, cb = (lane & 3) * 2;
#pragma unroll
    for (int mt = 0; mt < 2; mt++)
#pragma unroll
        for (int np = 0; np < 2; np++) {
            const int gm0 = bm + wm + mt * 16 + rb;
            const int gm1 = gm0 + 8;
            const int gn = bn + wn + np * 8 + cb;
            const float b0 = bias[gn], b1 = bias[gn + 1];
            *(float2*)(C + (size_t)gm0 * N + gn) =
                make_float2(acc[mt][np][0] + b0, acc[mt][np][1] + b1);
            *(float2*)(C + (size_t)gm1 * N + gn) =
                make_float2(acc[mt][np][2] + b0, acc[mt][np][3] + b1);
        }
}

// GEMM C: both operands staged from global (A = ctx).
__device__ __forceinline__ void gemm_phase64(
    const bf16* __restrict__ Ah, const bf16* __restrict__ Al,
    const bf16* __restrict__ Bh, const bf16* __restrict__ Bl,
    const float* __restrict__ bias, float* __restrict__ C,
    int N, int bm, int bn, char* raw)
{
    bf16* sAh = (bf16*)raw;
    bf16* sAl = sAh + 64 * PPAD;
    bf16* sBh = sAl + 64 * PPAD;
    bf16* sBl = sBh + 64 * PPAD;

    const int tid = threadIdx.x;
    const int warp = tid >> 5, lane = tid & 31;
    const int wm = (warp & 1) * 32, wn = (warp >> 1) * 16;
    const int row = tid >> 2, col = (tid & 3) * 8;
    const size_t abase = (size_t)(bm + row) * KDIM + col;
    const size_t bbase = (size_t)(bn + row) * KDIM + col;
    const int soff = row * PPAD + col;

    float acc[2][2][4];
#pragma unroll
    for (int i = 0; i < 2; i++)
#pragma unroll
        for (int j = 0; j < 2; j++)
#pragma unroll
            for (int v = 0; v < 4; v++) acc[i][j][v] = 0.0f;

    uint4 pa0 = *(const uint4*)(Ah + abase);
    uint4 pa1 = *(const uint4*)(Al + abase);
    uint4 pb0 = *(const uint4*)(Bh + bbase);
    uint4 pb1 = *(const uint4*)(Bl + bbase);

    const int nk = KDIM / 32;
    for (int kt = 0; kt < nk; kt++) {
        *(uint4*)&sAh[soff] = pa0; *(uint4*)&sAl[soff] = pa1;
        *(uint4*)&sBh[soff] = pb0; *(uint4*)&sBl[soff] = pb1;
        __syncthreads();

        if (kt + 1 < nk) {
            const int k0 = (kt + 1) * 32;
            pa0 = *(const uint4*)(Ah + abase + k0);
            pa1 = *(const uint4*)(Al + abase + k0);
            pb0 = *(const uint4*)(Bh + bbase + k0);
            pb1 = *(const uint4*)(Bl + bbase + k0);
        }

#pragma unroll
        for (int kc = 0; kc < 2; kc++) {
            uint32_t ah[2][4], al[2][4], bh[2][2], bl[2][2];
            const int acol = kc * 16 + (lane >> 4) * 8;
            const int arow = lane & 15;
#pragma unroll
            for (int mt = 0; mt < 2; mt++) {
                const int r = wm + mt * 16 + arow;
                ldsm4(ah[mt], &sAh[r * PPAD + acol]);
                ldsm4(al[mt], &sAl[r * PPAD + acol]);
            }
            const int bcol = kc * 16 + ((lane >> 3) & 1) * 8;
            const int brow = (lane & 7) + (lane >> 4) * 8;
            {
                const int r = wn + brow;
                uint32_t t[4];
                ldsm4(t, &sBh[r * PPAD + bcol]);
                bh[0][0] = t[0]; bh[0][1] = t[1];
                bh[1][0] = t[2]; bh[1][1] = t[3];
                ldsm4(t, &sBl[r * PPAD + bcol]);
                bl[0][0] = t[0]; bl[0][1] = t[1];
                bl[1][0] = t[2]; bl[1][1] = t[3];
            }
#pragma unroll
            for (int mt = 0; mt < 2; mt++)
#pragma unroll
                for (int np = 0; np < 2; np++) {
                    mma_bf16(acc[mt][np], ah[mt], bh[np]);
                    mma_bf16(acc[mt][np], ah[mt], bl[np]);
                    mma_bf16(acc[mt][np], al[mt], bh[np]);
                }
        }
        __syncthreads();
    }

    const int rb = lane >> 2, cb = (lane & 3) * 2;
#pragma unroll
    for (int mt = 0; mt < 2; mt++)
#pragma unroll
        for (int np = 0; np < 2; np++) {
            const int gm0 = bm + wm + mt * 16 + rb;
            const int gm1 = gm0 + 8;
            const int gn = bn + wn + np * 8 + cb;
            const float b0 = bias[gn], b1 = bias[gn + 1];
            *(float2*)(C + (size_t)gm0 * N + gn) =
                make_float2(acc[mt][np][0] + b0, acc[mt][np][1] + b1);
            *(float2*)(C + (size_t)gm1 * N + gn) =
                make_float2(acc[mt][np][2] + b0, acc[mt][np][3] + b1);
        }
}

// attention: both batches interleaved
__device__ __forceinline__ void attn_phase2(
    int b0, const __half* __restrict__ fph, const float* __restrict__ hgh,
    const float* __restrict__ ws, const __half* __restrict__ featsh,
    bf16* __restrict__ ctx_h, bf16* __restrict__ ctx_l, char* raw)
{
    AttnSmem* sm = (AttnSmem*)raw;
    const int b1 = b0 + 1;
    const int tid = threadIdx.x;
    const int warp = tid >> 5, lane = tid & 31;

    __syncthreads();
    for (int i = tid; i < NH; i += NTHR) {
        sm->hp0[i] = hgh[b0 * 4 * NH + i];
        sm->hp1[i] = hgh[b1 * 4 * NH + i];
        sm->ws[i]  = ws[i];
    }
    __syncthreads();

    // scores, both batches per warp iteration
    for (int t = warp; t < T_STEPS; t += 8) {
        const __half2* fpr0 = (const __half2*)(fph + ((size_t)t * NB + b0) * NH);
        const __half2* fpr1 = (const __half2*)(fph + ((size_t)t * NB + b1) * NH);
        float sum0 = 0.0f, sum1 = 0.0f;
#pragma unroll
        for (int i = 0; i < NH / 64; i++) {
            const int h2 = lane + i * 32;
            const float2 v0 = __half22float2(fpr0[h2]);
            const float2 v1 = __half22float2(fpr1[h2]);
            const int h = h2 * 2;
            const float w0 = sm->ws[h], w1 = sm->ws[h + 1];
            sum0 = fmaf(fast_tanh(v0.x + sm->hp0[h]),     w0, sum0);
            sum0 = fmaf(fast_tanh(v0.y + sm->hp0[h + 1]), w1, sum0);
            sum1 = fmaf(fast_tanh(v1.x + sm->hp1[h]),     w0, sum1);
            sum1 = fmaf(fast_tanh(v1.y + sm->hp1[h + 1]), w1, sum1);
        }
#pragma unroll
        for (int o = 16; o; o >>= 1) {
            sum0 += __shfl_xor_sync(0xffffffffu, sum0, o);
            sum1 += __shfl_xor_sync(0xffffffffu, sum1, o);
        }
        if (lane == 0) { sm->e0[t] = sum0; sm->e1[t] = sum1; }
    }
    __syncthreads();

    // softmax per batch (cheap)
#pragma unroll
    for (int pb = 0; pb < 2; pb++) {
        float* e = pb ? sm->e1 : sm->e0;
        float v = (tid < T_STEPS) ? e[tid] : -INFINITY;
        float m = v;
#pragma unroll
        for (int o = 16; o; o >>= 1) m = fmaxf(m, __shfl_xor_sync(0xffffffffu, m, o));
        if (lane == 0) sm->rmax[warp] = m;
        __syncthreads();
        float m0 = sm->rmax[0];
#pragma unroll
        for (int w = 1; w < 8; w++) m0 = fmaxf(m0, sm->rmax[w]);
        const float ev = (tid < T_STEPS) ? __expf(v - m0) : 0.0f;
        float s = ev;
#pragma unroll
        for (int o = 16; o; o >>= 1) s += __shfl_xor_sync(0xffffffffu, s, o);
        if (lane == 0) sm->rsum[warp] = s;
        __syncthreads();
        float tot = 0.0f;
#pragma unroll
        for (int w = 0; w < 8; w++) tot += sm->rsum[w];
        if (tid < T_STEPS) e[tid] = ev * __fdividef(1.0f, tot);
        __syncthreads();
    }

    // context, both batches interleaved (MLP 8)
    {
        const int c2 = tid;
        float a00 = 0.0f, a01 = 0.0f, a10 = 0.0f, a11 = 0.0f;
        const __half2* base0 = (const __half2*)(featsh + (size_t)b0 * NC) + c2;
        const __half2* base1 = (const __half2*)(featsh + (size_t)b1 * NC) + c2;
#pragma unroll 4
        for (int t = 0; t < T_STEPS; t++) {
            const size_t off = (size_t)t * NB * (NC / 2);
            const float2 f0 = __half22float2(base0[off]);
            const float2 f1 = __half22float2(base1[off]);
            const float w0 = sm->e0[t], w1 = sm->e1[t];
            a00 = fmaf(w0, f0.x, a00); a01 = fmaf(w0, f0.y, a01);
            a10 = fmaf(w1, f1.x, a10); a11 = fmaf(w1, f1.y, a11);
        }
        const int c = c2 * 2;
        bf16 h0, l0, h1, l1;
        split_bf16(a00, h0, l0); split_bf16(a01, h1, l1);
        ctx_h[b0 * NC + c] = h0;  ctx_h[b0 * NC + c + 1] = h1;
        ctx_l[b0 * NC + c] = l0;  ctx_l[b0 * NC + c + 1] = l1;
        split_bf16(a10, h0, l0); split_bf16(a11, h1, l1);
        ctx_h[b1 * NC + c] = h0;  ctx_h[b1 * NC + c + 1] = h1;
        ctx_l[b1 * NC + c] = l0;  ctx_l[b1 * NC + c + 1] = l1;
    }
}

__global__ __launch_bounds__(NTHR, 1) void persistent_steps(
    const __half* __restrict__ fph, const __half* __restrict__ featsh,
    const bf16* __restrict__ Wcat_h, const bf16* __restrict__ Wcat_l,
    const float* __restrict__ bcat,
    const bf16* __restrict__ Wih_h, const bf16* __restrict__ Wih_l,
    const float* __restrict__ b_ih, const float* __restrict__ ws,
    float* __restrict__ hgh0, float* __restrict__ hgh1,
    float* __restrict__ gi,
    bf16* __restrict__ ctx_h, bf16* __restrict__ ctx_l,
    bf16* __restrict__ hs_h, bf16* __restrict__ hs_l)
{
    extern __shared__ __align__(16) char dynsmem[];
    bf16* sh_hi = (bf16*)dynsmem;
    bf16* sh_lo = sh_hi + H_ELEMS;
    char* raw   = (char*)(sh_lo + H_ELEMS);

    const int blk = blockIdx.x;
    const int tid = threadIdx.x;
    const int tm = blk & 3, tn = blk >> 2;
    const int bm = tm * 64;

    // init own h rows to zero (h0 = 0)
    for (int i = tid; i < H_ELEMS; i += NTHR) {
        sh_hi[i] = __float2bfloat16(0.0f);
        sh_lo[i] = __float2bfloat16(0.0f);
    }
    // no __syncthreads needed: gemm_phaseA's first sync covers it.

    for (int s = 0; s < NL; s++) {
        float* hghC = (s & 1) ? hgh1 : hgh0;

        // A: [hp|gh] = h @ Wcat^T + bcat  (A from smem h)
        gemm_phaseA(sh_hi, sh_lo, Wcat_h, Wcat_l, bcat, hghC,
                    4 * NH, bm, tn * 64, raw);
        gbar(s * 3 + 0);

        // B: attention (2 batches, interleaved)
        attn_phase2(blk * 2, fph, hghC, ws, featsh, ctx_h, ctx_l, raw);
        gbar(s * 3 + 1);

        // C: gi = ctx @ Wih^T + b_ih
        if (tn < 24)
            gemm_phase64(ctx_h, ctx_l, Wih_h, Wih_l, b_ih, gi,
                         3 * NH, tm * 64, tn * 64, raw);
        gbar(s * 3 + 2);

        // GRU for own 64 rows (replicated across the 32 CTAs sharing tm).
        for (int e = tid; e < 64 * NH; e += NTHR) {
            const int lr = e >> 9, hh = e & (NH - 1);
            const int b = bm + lr;
            const float* gib = gi + b * 3 * NH;
            const float* ghb = hghC + b * 4 * NH + NH;
            const float r = fast_sigmoid(gib[hh]          + ghb[hh]);
            const float z = fast_sigmoid(gib[NH + hh]     + ghb[NH + hh]);
            const float n = fast_tanh   (gib[2 * NH + hh] + r * ghb[2 * NH + hh]);
            const int ho = lr * HPAD + hh;
            const float hprev = __bfloat162float(sh_hi[ho]) + __bfloat162float(sh_lo[ho]);
            const float hnew = (1.0f - z) * n + z * hprev;
            bf16 hi, lo;
            split_bf16(hnew, hi, lo);
            sh_hi[ho] = hi;
            sh_lo[ho] = lo;
            if (tn == 0) {
                const size_t o = ((size_t)b * NL + s) * NH + hh;
                hs_h[o] = hi;
                hs_l[o] = lo;
            }
        }
        // next gemm_phaseA's first __syncthreads orders these smem writes.
    }
}

// ---------- setup helpers ----------------------------------------------------
__global__ void reset_bar_kernel() {
    const int i = threadIdx.x;
    if (i < NSLOTS) g_bar_cnt[i] = 0u;
}
__global__ void split_kernel(const float* __restrict__ src,
                             bf16* __restrict__ hi, bf16* __restrict__ lo, int n)
{
    const int i = blockIdx.x * 256 + threadIdx.x;
    if (i < n) {
        bf16 h, l;
        split_bf16(src[i], h, l);
        hi[i] = h; lo[i] = l;
    }
}
__global__ void concat_split_kernel(const float* __restrict__ W_h2h,
                                    const float* __restrict__ W_hh,
                                    const float* __restrict__ b_h2h,
                                    const float* __restrict__ b_hh,
                                    bf16* __restrict__ Wh, bf16* __restrict__ Wl,
                                    float* __restrict__ bcat)
{
    const int i = blockIdx.x * 256 + threadIdx.x;
    const int total = 4 * NH * NH;
    if (i < total) {
        const int row = i / NH;
        const float x = (row < NH) ? W_h2h[i] : W_hh[i - NH * NH];
        bf16 h, l;
        split_bf16(x, h, l);
        Wh[i] = h; Wl[i] = l;
    }
    if (i < 4 * NH)
        bcat[i] = (i < NH) ? b_h2h[i] : b_hh[i - NH];
}
__global__ void f2h_kernel(const float* __restrict__ src, __half* __restrict__ dst,
                           int n2)
{
    const int i = blockIdx.x * 256 + threadIdx.x;
    if (i < n2) {
        const float2 v = ((const float2*)src)[i];
        ((__half2*)dst)[i] = __floats2half2_rn(v.x, v.y);
    }
}

// ---------------------------------------------------------------------------
extern "C" void kernel_launch(void* const* d_in, const int* in_sizes, int n_in,
                              void* d_out, int out_size)
{
    const float* feats   = (const float*)d_in[0];
    const float* W_i2h   = (const float*)d_in[2];
    const float* W_h2h   = (const float*)d_in[3];
    const float* b_h2h   = (const float*)d_in[4];
    const float* W_score = (const float*)d_in[5];
    const float* W_ih    = (const float*)d_in[6];
    const float* W_hh    = (const float*)d_in[7];
    const float* b_ih    = (const float*)d_in[8];
    const float* b_hh    = (const float*)d_in[9];
    const float* W_gen   = (const float*)d_in[10];
    const float* b_gen   = (const float*)d_in[11];
    float* out = (float*)d_out;

    bf16 *feats_h = 0, *feats_l = 0, *Wcat_h = 0, *Wcat_l = 0;
    bf16 *Wih_h = 0, *Wih_l = 0, *Wi2h_h = 0, *Wi2h_l = 0;
    bf16 *Wgen_h = 0, *Wgen_l = 0, *ctx_h = 0, *ctx_l = 0;
    bf16 *hs_h = 0, *hs_l = 0;
    float *bcat = 0, *hgh = 0, *gi = 0;
    __half *fph = 0, *featsh = 0;
    cudaGetSymbolAddress((void**)&feats_h, g_feats_h);
    cudaGetSymbolAddress((void**)&feats_l, g_feats_l);
    cudaGetSymbolAddress((void**)&fph,     g_fph);
    cudaGetSymbolAddress((void**)&featsh,  g_featsh);
    cudaGetSymbolAddress((void**)&Wcat_h,  g_Wcat_h);
    cudaGetSymbolAddress((void**)&Wcat_l,  g_Wcat_l);
    cudaGetSymbolAddress((void**)&bcat,    g_bcat);
    cudaGetSymbolAddress((void**)&Wih_h,   g_Wih_h);
    cudaGetSymbolAddress((void**)&Wih_l,   g_Wih_l);
    cudaGetSymbolAddress((void**)&Wi2h_h,  g_Wi2h_h);
    cudaGetSymbolAddress((void**)&Wi2h_l,  g_Wi2h_l);
    cudaGetSymbolAddress((void**)&Wgen_h,  g_Wgen_h);
    cudaGetSymbolAddress((void**)&Wgen_l,  g_Wgen_l);
    cudaGetSymbolAddress((void**)&hgh,     g_hgh);
    cudaGetSymbolAddress((void**)&gi,      g_gi);
    cudaGetSymbolAddress((void**)&ctx_h,   g_ctx_h);
    cudaGetSymbolAddress((void**)&ctx_l,   g_ctx_l);
    cudaGetSymbolAddress((void**)&hs_h,    g_hs_h);
    cudaGetSymbolAddress((void**)&hs_l,    g_hs_l);
    float* hgh0 = hgh;
    float* hgh1 = hgh + NB * 4 * NH;

    static bool attr_set = false;
    if (!attr_set) {
        cudaFuncSetAttribute(persistent_steps,
                             cudaFuncAttributeMaxDynamicSharedMemorySize, DYN_SMEM);
        attr_set = true;
    }

    // ---- setup ----
    {
        const int n = T_STEPS * NB * NC;
        split_kernel<<<(n + 255) / 256, 256>>>(feats, feats_h, feats_l, n);
        f2h_kernel<<<(n / 2 + 255) / 256, 256>>>(feats, featsh, n / 2);
    }
    concat_split_kernel<<<(4 * NH * NH + 255) / 256, 256>>>(
        W_h2h, W_hh, b_h2h, b_hh, Wcat_h, Wcat_l, bcat);
    split_kernel<<<(3 * NH * NC + 255) / 256, 256>>>(W_ih, Wih_h, Wih_l, 3 * NH * NC);
    split_kernel<<<(NH * NC + 255) / 256, 256>>>(W_i2h, Wi2h_h, Wi2h_l, NH * NC);
    split_kernel<<<(NCLS * NH + 255) / 256, 256>>>(W_gen, Wgen_h, Wgen_l, NCLS * NH);

    // feats_proj (fp16 out) = feats @ W_i2h^T
    {
        dim3 grid(NH / 128, (T_STEPS * NB) / 128);
        gemm_bf16split<true><<<grid, 256>>>(feats_h, feats_l, Wi2h_h, Wi2h_l,
                                            nullptr, fph, T_STEPS * NB, NH, KDIM);
    }

    // ---- recurrence: one persistent kernel ----
    reset_bar_kernel<<<1, 128>>>();
    persistent_steps<<<NBLK, NTHR, DYN_SMEM>>>(
        fph, featsh, Wcat_h, Wcat_l, bcat,
        Wih_h, Wih_l, b_ih, W_score,
        hgh0, hgh1, gi, ctx_h, ctx_l, hs_h, hs_l);

    // ---- generator ----
    {
        dim3 grid((NCLS + 127) / 128, (NB * NL) / 128);
        gemm_bf16split<false><<<grid, 256>>>(hs_h, hs_l, Wgen_h, Wgen_l,
                                             b_gen, out, NB * NL, NCLS, KDIM);
    }
}